// round 4
// baseline (speedup 1.0000x reference)
#include <cuda_runtime.h>
#include <math.h>
#include <stdint.h>

#define SEQ    256
#define BATCH  32
#define REC    16
#define EMB    32
#define VOCAB  32000
#define NROWS  (SEQ*BATCH)      // 8192
#define NRS    (NROWS/16)       // 512 row-strips of 16
#define NVR    32               // vocab ranges
#define VRNG   (VOCAB/NVR)      // 1000
#define NSUB   (VRNG/8)         // 125 subtiles per unit
#define NUNITS (NRS*NVR)        // 16384
#define GRIDP  592              // 148 SMs x 4 blocks

// ---- scratch ----
__device__ float g_ih[NROWS*REC];
__device__ float g_hidden[NROWS*REC];
__device__ __align__(16) float4 g_vtp[4*VOCAB];     // [t][v]: {k=t,t+4,t+8,t+12} tf32
__device__ __align__(16) float g_partial[NROWS*NVR]; // per-(row, vrange) sumexp
__device__ int g_ctr[2];

__device__ __forceinline__ uint32_t tf32u(float x) {
    uint32_t r;
    asm("cvt.rna.tf32.f32 %0, %1;" : "=r"(r) : "f"(x));
    return r;
}

__device__ __forceinline__ void mma1684(float& c0, float& c1, float& c2, float& c3,
                                        uint32_t a0, uint32_t a1, uint32_t b0) {
    asm volatile("mma.sync.aligned.m16n8k4.row.col.f32.tf32.tf32.f32 "
                 "{%0,%1,%2,%3}, {%4,%5}, {%6}, {%0,%1,%2,%3};"
                 : "+f"(c0), "+f"(c1), "+f"(c2), "+f"(c3)
                 : "r"(a0), "r"(a1), "r"(b0));
}

// ---------- kernel 0: pack V -> g_vtp (tf32-rounded), reset work counters ----------
__global__ void pack_kernel(const float* __restrict__ Vm) {
    int v = blockIdx.x * 256 + threadIdx.x;
    if (blockIdx.x == 0 && threadIdx.x < 2) g_ctr[threadIdx.x] = 0;
    const float4* vr = (const float4*)(Vm + (size_t)v * REC);
    float4 a = vr[0], b = vr[1], c = vr[2], d = vr[3];  // k0-3, k4-7, k8-11, k12-15
    float4 o;
    o.x = __uint_as_float(tf32u(a.x)); o.y = __uint_as_float(tf32u(b.x));
    o.z = __uint_as_float(tf32u(c.x)); o.w = __uint_as_float(tf32u(d.x));
    g_vtp[0*VOCAB + v] = o;
    o.x = __uint_as_float(tf32u(a.y)); o.y = __uint_as_float(tf32u(b.y));
    o.z = __uint_as_float(tf32u(c.y)); o.w = __uint_as_float(tf32u(d.y));
    g_vtp[1*VOCAB + v] = o;
    o.x = __uint_as_float(tf32u(a.z)); o.y = __uint_as_float(tf32u(b.z));
    o.z = __uint_as_float(tf32u(c.z)); o.w = __uint_as_float(tf32u(d.z));
    g_vtp[2*VOCAB + v] = o;
    o.x = __uint_as_float(tf32u(a.w)); o.y = __uint_as_float(tf32u(b.w));
    o.z = __uint_as_float(tf32u(c.w)); o.w = __uint_as_float(tf32u(d.w));
    g_vtp[3*VOCAB + v] = o;
}

// ---------- kernel 1: i_h = emb[input] @ U^T + b1 ----------
__global__ void ih_kernel(const int* __restrict__ inp, const float* __restrict__ emb,
                          const float* __restrict__ U, const float* __restrict__ b1) {
    __shared__ float Us[REC*EMB];
    int tid = threadIdx.x;
    for (int i = tid; i < REC*EMB; i += 256) Us[i] = U[i];
    __syncthreads();
    int row = blockIdx.x * 16 + (tid >> 4);
    int r   = tid & 15;
    int idx = inp[row];
    const float* e = emb + (size_t)idx * EMB;
    float acc = b1[r];
#pragma unroll
    for (int k = 0; k < EMB; k++) acc += e[k] * Us[r*EMB + k];
    g_ih[row*REC + r] = acc;
}

// ---------- kernel 2: serial recurrence (1 block, 512 thr = 32 b x 16 r) ----------
__global__ void rnn_kernel(const float* __restrict__ W, const float* __restrict__ b2,
                           const float* __restrict__ h0v) {
    __shared__ __align__(16) float hs[BATCH*REC];
    int tid = threadIdx.x;
    int b = tid >> 4, r = tid & 15;
    float w[REC];
#pragma unroll
    for (int k = 0; k < REC; k++) w[k] = W[r*REC + k];
    float bias = b2[r];
    float h = h0v[r];
    hs[tid] = h;
    g_hidden[tid] = h;
    __syncthreads();
    float ihv = g_ih[tid];
    for (int t = 0; t < SEQ-1; t++) {
        float ihn = 0.f;
        if (t < SEQ-2) ihn = g_ih[(t+1)*(BATCH*REC) + tid];
        const float4* hp = (const float4*)(hs + b*REC);
        float4 p0 = hp[0], p1 = hp[1], p2 = hp[2], p3 = hp[3];
        float acc = ihv + bias;
        acc += p0.x*w[0]  + p0.y*w[1]  + p0.z*w[2]  + p0.w*w[3];
        acc += p1.x*w[4]  + p1.y*w[5]  + p1.z*w[6]  + p1.w*w[7];
        acc += p2.x*w[8]  + p2.y*w[9]  + p2.z*w[10] + p2.w*w[11];
        acc += p3.x*w[12] + p3.y*w[13] + p3.z*w[14] + p3.w*w[15];
        float hn = tanhf(acc);
        __syncthreads();
        hs[tid] = hn;
        g_hidden[(size_t)(t+1)*(BATCH*REC) + tid] = hn;
        __syncthreads();
        ihv = ihn;
    }
}

// ---------- main GEMM: per-warp work queue over 16384 units ----------
// Unit u: row-strip rs = u & 511 (16 rows), vocab range vr = u >> 9 (1000 vocab).
// D[16 x 8] per subtile via 4x mma.m16n8k4 tf32.
// PASS 0: g_partial[row][vr] = sum_v exp(logit)   (deterministic, no atomics)
// PASS 1: out[row][v] = logit - log(sum_j partial[row][j])
template <int PASS>
__global__ __launch_bounds__(256, 4)
void mma_kernel(float* __restrict__ out) {
    int tid = threadIdx.x, lane = tid & 31;
    int g = lane >> 2, t = lane & 3;

    for (;;) {
        int u;
        if (lane == 0) u = atomicAdd(&g_ctr[PASS], 1);
        u = __shfl_sync(0xffffffffu, u, 0);
        if (u >= NUNITS) break;

        int rs = u & (NRS-1), vr = u >> 9;
        int rb = rs * 16, vb = vr * VRNG;

        // A fragments: rows rb+g, rb+g+8; col k = kc*4 + t
        const float* h0p = g_hidden + (size_t)(rb + g) * REC;
        const float* h1p = g_hidden + (size_t)(rb + g + 8) * REC;
        uint32_t A0[4], A1[4];
#pragma unroll
        for (int kc = 0; kc < 4; kc++) {
            A0[kc] = tf32u(h0p[kc*4 + t]);
            A1[kc] = tf32u(h1p[kc*4 + t]);
        }

        float nls0 = 0.f, nls1 = 0.f, s0 = 0.f, s1 = 0.f;
        if (PASS == 1) {
            const float4* p0 = (const float4*)(g_partial + (size_t)(rb + g) * NVR);
            const float4* p1 = (const float4*)(g_partial + (size_t)(rb + g + 8) * NVR);
            float a0 = 0.f, a1 = 0.f;
#pragma unroll
            for (int j = 0; j < NVR/4; j++) {
                float4 q0 = p0[j], q1 = p1[j];
                a0 += q0.x + q0.y + q0.z + q0.w;
                a1 += q1.x + q1.y + q1.z + q1.w;
            }
            nls0 = -__logf(a0);
            nls1 = -__logf(a1);
        }

        const float4* bp = g_vtp + (size_t)t * VOCAB + vb + g;
        float4 bq = bp[0];
        for (int s = 0; s < NSUB; s++) {
            float4 bn;
            if (s + 1 < NSUB) bn = bp[(s + 1) * 8];
            float c0 = 0.f, c1 = 0.f, c2 = 0.f, c3 = 0.f;
            mma1684(c0, c1, c2, c3, A0[0], A1[0], __float_as_uint(bq.x));
            mma1684(c0, c1, c2, c3, A0[1], A1[1], __float_as_uint(bq.y));
            mma1684(c0, c1, c2, c3, A0[2], A1[2], __float_as_uint(bq.z));
            mma1684(c0, c1, c2, c3, A0[3], A1[3], __float_as_uint(bq.w));
            if (PASS == 0) {
                s0 += __expf(c0) + __expf(c1);
                s1 += __expf(c2) + __expf(c3);
            } else {
                int col = vb + s*8 + 2*t;
                float2 o0 = make_float2(c0 + nls0, c1 + nls0);
                float2 o1 = make_float2(c2 + nls1, c3 + nls1);
                *(float2*)(out + (size_t)(rb + g) * VOCAB + col) = o0;
                *(float2*)(out + (size_t)(rb + g + 8) * VOCAB + col) = o1;
            }
            bq = bn;
        }

        if (PASS == 0) {
            // reduce over the 4 t-lanes sharing each row
            s0 += __shfl_xor_sync(0xffffffffu, s0, 1);
            s0 += __shfl_xor_sync(0xffffffffu, s0, 2);
            s1 += __shfl_xor_sync(0xffffffffu, s1, 1);
            s1 += __shfl_xor_sync(0xffffffffu, s1, 2);
            if (t == 0) {
                g_partial[(size_t)(rb + g) * NVR + vr] = s0;
                g_partial[(size_t)(rb + g + 8) * NVR + vr] = s1;
            }
        }
    }
}

extern "C" void kernel_launch(void* const* d_in, const int* in_sizes, int n_in,
                              void* d_out, int out_size) {
    const int*   inp = (const int*)d_in[0];
    const float* emb = (const float*)d_in[1];
    const float* U   = (const float*)d_in[2];
    const float* W   = (const float*)d_in[3];
    const float* Vm  = (const float*)d_in[4];
    const float* b1  = (const float*)d_in[5];
    const float* b2  = (const float*)d_in[6];
    const float* h0  = (const float*)d_in[7];
    float* out = (float*)d_out;

    pack_kernel<<<VOCAB/256, 256>>>(Vm);
    ih_kernel<<<NROWS/16, 256>>>(inp, emb, U, b1);
    rnn_kernel<<<1, BATCH*REC>>>(W, b2, h0);
    mma_kernel<0><<<GRIDP, 256>>>(out);
    mma_kernel<1><<<GRIDP, 256>>>(out);
}

// round 5
// speedup vs baseline: 1.0802x; 1.0802x over previous
#include <cuda_runtime.h>
#include <math.h>
#include <stdint.h>

#define SEQ    256
#define BATCH  32
#define REC    16
#define EMB    32
#define VOCAB  32000
#define NROWS  (SEQ*BATCH)      // 8192
#define NRS    (NROWS/16)       // 512 row-strips of 16
#define NVR    100              // vocab ranges
#define VRNG   (VOCAB/NVR)      // 320
#define NSUB   (VRNG/8)         // 40 subtiles per unit
#define NUNITS (NRS*NVR)        // 51200
#define GRIDP  740              // 148 SMs x 5 blocks

// ---- scratch ----
__device__ float g_ih[NROWS*REC];
__device__ float g_hidden[NROWS*REC];
__device__ __align__(16) float4 g_vtp[4*VOCAB];       // [t][v]: {k=t,t+4,t+8,t+12} tf32
__device__ float g_partial[NVR*NROWS];                // [vr][row] partial sumexp
__device__ float g_lse[NROWS];                        // -log(sumexp)
__device__ int g_ctr[2];

__device__ __forceinline__ uint32_t tf32u(float x) {
    uint32_t r;
    asm("cvt.rna.tf32.f32 %0, %1;" : "=r"(r) : "f"(x));
    return r;
}
__device__ __forceinline__ void mma16888(float& c0, float& c1, float& c2, float& c3,
                                         const uint32_t* A, uint32_t b0, uint32_t b1) {
    asm volatile("mma.sync.aligned.m16n8k8.row.col.f32.tf32.tf32.f32 "
                 "{%0,%1,%2,%3}, {%4,%5,%6,%7}, {%8,%9}, {%0,%1,%2,%3};"
                 : "+f"(c0), "+f"(c1), "+f"(c2), "+f"(c3)
                 : "r"(A[0]), "r"(A[1]), "r"(A[2]), "r"(A[3]), "r"(b0), "r"(b1));
}
__device__ __forceinline__ void stcs2(float* p, float a, float b) {
    asm volatile("st.global.cs.v2.f32 [%0], {%1,%2};" :: "l"(p), "f"(a), "f"(b) : "memory");
}

// ---------- kernel 0: pack V -> g_vtp (tf32-rounded), reset work counters ----------
__global__ void pack_kernel(const float* __restrict__ Vm) {
    int v = blockIdx.x * 256 + threadIdx.x;
    if (blockIdx.x == 0 && threadIdx.x < 2) g_ctr[threadIdx.x] = 0;
    const float4* vr = (const float4*)(Vm + (size_t)v * REC);
    float4 a = vr[0], b = vr[1], c = vr[2], d = vr[3];
    float4 o;
    o.x = __uint_as_float(tf32u(a.x)); o.y = __uint_as_float(tf32u(b.x));
    o.z = __uint_as_float(tf32u(c.x)); o.w = __uint_as_float(tf32u(d.x));
    g_vtp[0*VOCAB + v] = o;
    o.x = __uint_as_float(tf32u(a.y)); o.y = __uint_as_float(tf32u(b.y));
    o.z = __uint_as_float(tf32u(c.y)); o.w = __uint_as_float(tf32u(d.y));
    g_vtp[1*VOCAB + v] = o;
    o.x = __uint_as_float(tf32u(a.z)); o.y = __uint_as_float(tf32u(b.z));
    o.z = __uint_as_float(tf32u(c.z)); o.w = __uint_as_float(tf32u(d.z));
    g_vtp[2*VOCAB + v] = o;
    o.x = __uint_as_float(tf32u(a.w)); o.y = __uint_as_float(tf32u(b.w));
    o.z = __uint_as_float(tf32u(c.w)); o.w = __uint_as_float(tf32u(d.w));
    g_vtp[3*VOCAB + v] = o;
}

// ---------- kernel 1: i_h = emb[input] @ U^T + b1 ----------
__global__ void ih_kernel(const int* __restrict__ inp, const float* __restrict__ emb,
                          const float* __restrict__ U, const float* __restrict__ b1) {
    __shared__ float Us[REC*EMB];
    int tid = threadIdx.x;
    for (int i = tid; i < REC*EMB; i += 256) Us[i] = U[i];
    __syncthreads();
    int row = blockIdx.x * 16 + (tid >> 4);
    int r   = tid & 15;
    int idx = inp[row];
    const float* e = emb + (size_t)idx * EMB;
    float acc = b1[r];
#pragma unroll
    for (int k = 0; k < EMB; k++) acc += e[k] * Us[r*EMB + k];
    g_ih[row*REC + r] = acc;
}

// ---------- kernel 2: serial recurrence ----------
__global__ void rnn_kernel(const float* __restrict__ W, const float* __restrict__ b2,
                           const float* __restrict__ h0v) {
    __shared__ __align__(16) float hs[BATCH*REC];
    int tid = threadIdx.x;
    int b = tid >> 4, r = tid & 15;
    float w[REC];
#pragma unroll
    for (int k = 0; k < REC; k++) w[k] = W[r*REC + k];
    float bias = b2[r];
    float h = h0v[r];
    hs[tid] = h;
    g_hidden[tid] = h;
    __syncthreads();
    float ihv = g_ih[tid];
    for (int t = 0; t < SEQ-1; t++) {
        float ihn = 0.f;
        if (t < SEQ-2) ihn = g_ih[(t+1)*(BATCH*REC) + tid];
        const float4* hp = (const float4*)(hs + b*REC);
        float4 p0 = hp[0], p1 = hp[1], p2 = hp[2], p3 = hp[3];
        float acc = ihv + bias;
        acc += p0.x*w[0]  + p0.y*w[1]  + p0.z*w[2]  + p0.w*w[3];
        acc += p1.x*w[4]  + p1.y*w[5]  + p1.z*w[6]  + p1.w*w[7];
        acc += p2.x*w[8]  + p2.y*w[9]  + p2.z*w[10] + p2.w*w[11];
        acc += p3.x*w[12] + p3.y*w[13] + p3.z*w[14] + p3.w*w[15];
        float hn = tanhf(acc);
        __syncthreads();
        hs[tid] = hn;
        g_hidden[(size_t)(t+1)*(BATCH*REC) + tid] = hn;
        __syncthreads();
        ihv = ihn;
    }
}

// ---------- kernel 3: lse over partials ----------
__global__ void lse_kernel() {
    int row = blockIdx.x * 256 + threadIdx.x;
    float a = 0.f;
#pragma unroll 10
    for (int j = 0; j < NVR; j++) a += g_partial[j*NROWS + row];
    g_lse[row] = -__logf(a);
}

// ---------- main GEMM: per-warp work queue over 51200 units ----------
// Unit u: row-strip rs = u & 511 (16 rows), vocab range vr = u >> 9 (320 vocab).
// PASS 0: g_partial[vr][row] = sum_v exp(logit)
// PASS 1: out[row][v] = logit + g_lse[row]   (g_lse = -log sumexp)
template <int PASS>
__global__ __launch_bounds__(256, 5)
void mma_kernel(float* __restrict__ out) {
    int lane = threadIdx.x & 31;
    int g = lane >> 2, t = lane & 3;

    int u;
    if (lane == 0) u = atomicAdd(&g_ctr[PASS], 1);
    u = __shfl_sync(0xffffffffu, u, 0);

    while (u < NUNITS) {
        int un;
        if (lane == 0) un = atomicAdd(&g_ctr[PASS], 1);  // prefetch next unit

        int rs = u & (NRS-1), vr = u >> 9;
        int rb = rs * 16, vb = vr * VRNG;

        const float* h0p = g_hidden + (size_t)(rb + g) * REC;
        const float* h1p = g_hidden + (size_t)(rb + g + 8) * REC;
        uint32_t A1[4], A2[4];
        A1[0] = tf32u(h0p[t]);      A1[1] = tf32u(h1p[t]);
        A1[2] = tf32u(h0p[t + 4]);  A1[3] = tf32u(h1p[t + 4]);
        A2[0] = tf32u(h0p[t + 8]);  A2[1] = tf32u(h1p[t + 8]);
        A2[2] = tf32u(h0p[t + 12]); A2[3] = tf32u(h1p[t + 12]);

        float nls0 = 0.f, nls1 = 0.f, s0 = 0.f, s1 = 0.f;
        if (PASS == 1) { nls0 = g_lse[rb + g]; nls1 = g_lse[rb + g + 8]; }

        const float4* bp = g_vtp + (size_t)t * VOCAB + vb + g;
        float4 b0 = bp[0], b1 = bp[8];
        float* o0 = out + (size_t)(rb + g) * VOCAB + vb + 2*t;
        float* o1 = out + (size_t)(rb + g + 8) * VOCAB + vb + 2*t;

        for (int s = 0; s < NSUB; s += 2) {
            float4 n0, n1;
            if (s + 2 < NSUB) { n0 = bp[(s+2)*8]; n1 = bp[(s+3)*8]; }
            // subtile s and s+1: 4 MMAs, two independent accumulator sets
            float c0=0.f, c1=0.f, c2=0.f, c3=0.f;
            float d0=0.f, d1=0.f, d2=0.f, d3=0.f;
            mma16888(c0, c1, c2, c3, A1, __float_as_uint(b0.x), __float_as_uint(b0.y));
            mma16888(d0, d1, d2, d3, A1, __float_as_uint(b1.x), __float_as_uint(b1.y));
            mma16888(c0, c1, c2, c3, A2, __float_as_uint(b0.z), __float_as_uint(b0.w));
            mma16888(d0, d1, d2, d3, A2, __float_as_uint(b1.z), __float_as_uint(b1.w));
            if (PASS == 0) {
                s0 += __expf(c0) + __expf(c1) + __expf(d0) + __expf(d1);
                s1 += __expf(c2) + __expf(c3) + __expf(d2) + __expf(d3);
            } else {
                stcs2(o0 + s*8,     c0 + nls0, c1 + nls0);
                stcs2(o0 + s*8 + 8, d0 + nls0, d1 + nls0);
                stcs2(o1 + s*8,     c2 + nls1, c3 + nls1);
                stcs2(o1 + s*8 + 8, d2 + nls1, d3 + nls1);
            }
            b0 = n0; b1 = n1;
        }

        if (PASS == 0) {
            s0 += __shfl_xor_sync(0xffffffffu, s0, 1);
            s0 += __shfl_xor_sync(0xffffffffu, s0, 2);
            s1 += __shfl_xor_sync(0xffffffffu, s1, 1);
            s1 += __shfl_xor_sync(0xffffffffu, s1, 2);
            if (t == 0) {
                g_partial[(size_t)vr*NROWS + rb + g]     = s0;
                g_partial[(size_t)vr*NROWS + rb + g + 8] = s1;
            }
        }

        un = __shfl_sync(0xffffffffu, un, 0);
        u = un;
    }
}

extern "C" void kernel_launch(void* const* d_in, const int* in_sizes, int n_in,
                              void* d_out, int out_size) {
    const int*   inp = (const int*)d_in[0];
    const float* emb = (const float*)d_in[1];
    const float* U   = (const float*)d_in[2];
    const float* W   = (const float*)d_in[3];
    const float* Vm  = (const float*)d_in[4];
    const float* b1  = (const float*)d_in[5];
    const float* b2  = (const float*)d_in[6];
    const float* h0  = (const float*)d_in[7];
    float* out = (float*)d_out;

    pack_kernel<<<VOCAB/256, 256>>>(Vm);
    ih_kernel<<<NROWS/16, 256>>>(inp, emb, U, b1);
    rnn_kernel<<<1, BATCH*REC>>>(W, b2, h0);
    mma_kernel<0><<<GRIDP, 256>>>(out);
    lse_kernel<<<NROWS/256, 256>>>();
    mma_kernel<1><<<GRIDP, 256>>>(out);
}